// round 13
// baseline (speedup 1.0000x reference)
#include <cuda_runtime.h>
#include <cuda_bf16.h>

// VP_lattice reverse step.
// Inputs (metadata order):
//  0: lt           (B,6)   f32
//  1: predicted_l0 (B,6)   f32
//  2: pred_lattice (B,3,3) f32
//  3: alpha_bars   (1001,) f32
//  4: betas        (1001,) f32
//  5: sigmas       (1001,) f32
//  6: z_noise      (B,6)   f32
//  7: t            (B,)    int32   <-- JAX x64 disabled: int64 in source is int32 on device
// Output: (B,6) f32

#define ROWS_PER_BLOCK 256
#define NSWEEP 5

__device__ __forceinline__ void jrot(float* cp, float* cq, float* vp, float* vq) {
    float al = cp[0]*cp[0] + cp[1]*cp[1] + cp[2]*cp[2];
    float be = cq[0]*cq[0] + cq[1]*cq[1] + cq[2]*cq[2];
    float ga = cp[0]*cq[0] + cp[1]*cq[1] + cp[2]*cq[2];
    if (fabsf(ga) > 1e-28f) {
        float zeta = (be - al) / (2.0f * ga);
        float tt = copysignf(1.0f, zeta) / (fabsf(zeta) + sqrtf(1.0f + zeta*zeta));
        float c  = rsqrtf(1.0f + tt*tt);
        float s  = c * tt;
        #pragma unroll
        for (int i = 0; i < 3; i++) {
            float tp = cp[i], tq = cq[i];
            cp[i] = c*tp - s*tq;
            cq[i] = s*tp + c*tq;
            tp = vp[i]; tq = vq[i];
            vp[i] = c*tp - s*tq;
            vq[i] = s*tp + c*tq;
        }
    }
}

__global__ __launch_bounds__(ROWS_PER_BLOCK)
void vp_lattice_kernel(const float* __restrict__ lt,
                       const float* __restrict__ pl0,
                       const float* __restrict__ lat,
                       const float* __restrict__ alpha_bars,
                       const float* __restrict__ betas,
                       const float* __restrict__ sigmas,
                       const float* __restrict__ zn,
                       const int*  __restrict__ tarr,
                       float* __restrict__ out,
                       int beta_m2_idx,    // index of betas[-2]
                       int tmax_idx)       // last valid table index (nbetas-1)
{
    __shared__ float s_lt[ROWS_PER_BLOCK * 6];
    __shared__ float s_p0[ROWS_PER_BLOCK * 6];
    __shared__ float s_z [ROWS_PER_BLOCK * 6];
    __shared__ float s_A [ROWS_PER_BLOCK * 9];

    const int tid = threadIdx.x;
    const long long base = (long long)blockIdx.x * ROWS_PER_BLOCK;

    // ---- staged coalesced scalar loads ----
    {
        const float* g1 = lt  + base * 6;
        const float* g2 = pl0 + base * 6;
        const float* g3 = zn  + base * 6;
        #pragma unroll
        for (int i = tid; i < ROWS_PER_BLOCK * 6; i += ROWS_PER_BLOCK) {
            s_lt[i] = g1[i];
            s_p0[i] = g2[i];
            s_z [i] = g3[i];
        }
        const float* g4 = lat + base * 9;
        #pragma unroll
        for (int i = tid; i < ROWS_PER_BLOCK * 9; i += ROWS_PER_BLOCK) {
            s_A[i] = g4[i];
        }
    }
    const int tv = tarr[base + tid];
    // Defensive clamp: keeps table gathers in-bounds no matter what (no-op for valid t).
    int ti = tv < 0 ? 0 : (tv > tmax_idx ? tmax_idx : tv);
    __syncthreads();

    // ---- one-sided Jacobi SVD on 3x3 (columns of A) ----
    float c0[3], c1[3], c2[3];
    {
        const float* a = &s_A[tid * 9];  // row-major a[i*3+j]
        #pragma unroll
        for (int i = 0; i < 3; i++) {
            c0[i] = a[i*3 + 0];
            c1[i] = a[i*3 + 1];
            c2[i] = a[i*3 + 2];
        }
    }
    float v0[3] = {1.f, 0.f, 0.f};
    float v1[3] = {0.f, 1.f, 0.f};
    float v2[3] = {0.f, 0.f, 1.f};

    #pragma unroll
    for (int sw = 0; sw < NSWEEP; sw++) {
        jrot(c0, c1, v0, v1);
        jrot(c0, c2, v0, v2);
        jrot(c1, c2, v1, v2);
    }

    const float s0 = sqrtf(c0[0]*c0[0] + c0[1]*c0[1] + c0[2]*c0[2]);
    const float s1 = sqrtf(c1[0]*c1[0] + c1[1]*c1[1] + c1[2]*c1[2]);
    const float s2 = sqrtf(c2[0]*c2[0] + c2[1]*c2[1] + c2[2]*c2[2]);

    // L = V diag(s) V^T ; vec = [L00, L01, L02, L11, L12, L22]
    float vec[6];
    vec[0] = s0*v0[0]*v0[0] + s1*v1[0]*v1[0] + s2*v2[0]*v2[0];
    vec[1] = s0*v0[0]*v0[1] + s1*v1[0]*v1[1] + s2*v2[0]*v2[1];
    vec[2] = s0*v0[0]*v0[2] + s1*v1[0]*v1[2] + s2*v2[0]*v2[2];
    vec[3] = s0*v0[1]*v0[1] + s1*v1[1]*v1[1] + s2*v2[1]*v2[1];
    vec[4] = s0*v0[1]*v0[2] + s1*v1[1]*v1[2] + s2*v2[1]*v2[2];
    vec[5] = s0*v0[2]*v0[2] + s1*v1[2]*v1[2] + s2*v2[2]*v2[2];

    // ---- diffusion step scalars (tables are tiny; L2/L1-hot) ----
    const float beta_t   = betas[ti];
    const float beta_cap = betas[beta_m2_idx];   // betas[-2]
    float alpha = 1.0f - beta_t;
    alpha = fmaxf(alpha, 1.0f - beta_cap);
    const float alpha_bar = alpha_bars[ti];
    const float sigma     = sigmas[ti];

    const float coef  = rsqrtf(alpha + 1e-8f);
    const float scale = (1.0f - alpha) * rsqrtf(1.0f - alpha_bar + 1e-8f);
    const float zg    = (tv > 1) ? 1.0f : 0.0f;

    // ---- per-component output (write back into s_lt, reuse buffer) ----
    float* row_lt = &s_lt[tid * 6];
    const float* row_p0 = &s_p0[tid * 6];
    const float* row_z  = &s_z [tid * 6];
    #pragma unroll
    for (int k = 0; k < 6; k++) {
        const float ltv = row_lt[k];
        const float pn  = ltv - 0.5f * (vec[k] + row_p0[k]);
        row_lt[k] = coef * (ltv - scale * pn) + sigma * (zg * row_z[k]);
    }

    __syncthreads();

    // ---- staged coalesced scalar store ----
    {
        float* go = out + base * 6;
        #pragma unroll
        for (int i = tid; i < ROWS_PER_BLOCK * 6; i += ROWS_PER_BLOCK) {
            go[i] = s_lt[i];
        }
    }
}

extern "C" void kernel_launch(void* const* d_in, const int* in_sizes, int n_in,
                              void* d_out, int out_size) {
    const float* lt         = (const float*)d_in[0];
    const float* pl0        = (const float*)d_in[1];
    const float* lat        = (const float*)d_in[2];
    const float* alpha_bars = (const float*)d_in[3];
    const float* betas      = (const float*)d_in[4];
    const float* sigmas     = (const float*)d_in[5];
    const float* zn         = (const float*)d_in[6];
    const int*   tarr       = (const int*)d_in[7];   // int32 on device (JAX x64 off)
    float* out = (float*)d_out;

    const int rows   = in_sizes[7];             // B
    const int nbetas = in_sizes[4];             // NUM_STEPS + 1 = 1001
    const int blocks = rows / ROWS_PER_BLOCK;   // B = 2^20, divisible

    vp_lattice_kernel<<<blocks, ROWS_PER_BLOCK>>>(
        lt, pl0, lat, alpha_bars, betas, sigmas, zn, tarr, out,
        nbetas - 2, nbetas - 1);
}

// round 17
// speedup vs baseline: 1.0011x; 1.0011x over previous
#include <cuda_runtime.h>
#include <cuda_bf16.h>

// VP_lattice reverse step.
// Inputs (metadata order):
//  0: lt           (B,6)   f32
//  1: predicted_l0 (B,6)   f32
//  2: pred_lattice (B,3,3) f32
//  3: alpha_bars   (1001,) f32
//  4: betas        (1001,) f32
//  5: sigmas       (1001,) f32
//  6: z_noise      (B,6)   f32
//  7: t            (B,)    int32   <-- JAX x64 disabled: int64 in source is int32 on device
// Output: (B,6) f32

#define ROWS_PER_BLOCK 256
#define NSWEEP 5

__device__ __forceinline__ void jrot(float* cp, float* cq, float* vp, float* vq) {
    float al = cp[0]*cp[0] + cp[1]*cp[1] + cp[2]*cp[2];
    float be = cq[0]*cq[0] + cq[1]*cq[1] + cq[2]*cq[2];
    float ga = cp[0]*cq[0] + cp[1]*cq[1] + cp[2]*cq[2];
    if (fabsf(ga) > 1e-28f) {
        float zeta = (be - al) / (2.0f * ga);
        float tt = copysignf(1.0f, zeta) / (fabsf(zeta) + sqrtf(1.0f + zeta*zeta));
        float c  = rsqrtf(1.0f + tt*tt);
        float s  = c * tt;
        #pragma unroll
        for (int i = 0; i < 3; i++) {
            float tp = cp[i], tq = cq[i];
            cp[i] = c*tp - s*tq;
            cq[i] = s*tp + c*tq;
            tp = vp[i]; tq = vq[i];
            vp[i] = c*tp - s*tq;
            vq[i] = s*tp + c*tq;
        }
    }
}

__global__ __launch_bounds__(ROWS_PER_BLOCK)
void vp_lattice_kernel(const float* __restrict__ lt,
                       const float* __restrict__ pl0,
                       const float* __restrict__ lat,
                       const float* __restrict__ alpha_bars,
                       const float* __restrict__ betas,
                       const float* __restrict__ sigmas,
                       const float* __restrict__ zn,
                       const int*  __restrict__ tarr,
                       float* __restrict__ out,
                       int beta_m2_idx,    // index of betas[-2]
                       int tmax_idx)       // last valid table index (nbetas-1)
{
    __shared__ float s_lt[ROWS_PER_BLOCK * 6];
    __shared__ float s_p0[ROWS_PER_BLOCK * 6];
    __shared__ float s_z [ROWS_PER_BLOCK * 6];
    __shared__ float s_A [ROWS_PER_BLOCK * 9];

    const int tid = threadIdx.x;
    const long long base = (long long)blockIdx.x * ROWS_PER_BLOCK;

    // ---- staged coalesced scalar loads ----
    {
        const float* g1 = lt  + base * 6;
        const float* g2 = pl0 + base * 6;
        const float* g3 = zn  + base * 6;
        #pragma unroll
        for (int i = tid; i < ROWS_PER_BLOCK * 6; i += ROWS_PER_BLOCK) {
            s_lt[i] = g1[i];
            s_p0[i] = g2[i];
            s_z [i] = g3[i];
        }
        const float* g4 = lat + base * 9;
        #pragma unroll
        for (int i = tid; i < ROWS_PER_BLOCK * 9; i += ROWS_PER_BLOCK) {
            s_A[i] = g4[i];
        }
    }
    const int tv = tarr[base + tid];
    // Defensive clamp: keeps table gathers in-bounds no matter what (no-op for valid t).
    int ti = tv < 0 ? 0 : (tv > tmax_idx ? tmax_idx : tv);
    __syncthreads();

    // ---- one-sided Jacobi SVD on 3x3 (columns of A) ----
    float c0[3], c1[3], c2[3];
    {
        const float* a = &s_A[tid * 9];  // row-major a[i*3+j]
        #pragma unroll
        for (int i = 0; i < 3; i++) {
            c0[i] = a[i*3 + 0];
            c1[i] = a[i*3 + 1];
            c2[i] = a[i*3 + 2];
        }
    }
    float v0[3] = {1.f, 0.f, 0.f};
    float v1[3] = {0.f, 1.f, 0.f};
    float v2[3] = {0.f, 0.f, 1.f};

    #pragma unroll
    for (int sw = 0; sw < NSWEEP; sw++) {
        jrot(c0, c1, v0, v1);
        jrot(c0, c2, v0, v2);
        jrot(c1, c2, v1, v2);
    }

    const float s0 = sqrtf(c0[0]*c0[0] + c0[1]*c0[1] + c0[2]*c0[2]);
    const float s1 = sqrtf(c1[0]*c1[0] + c1[1]*c1[1] + c1[2]*c1[2]);
    const float s2 = sqrtf(c2[0]*c2[0] + c2[1]*c2[1] + c2[2]*c2[2]);

    // L = V diag(s) V^T ; vec = [L00, L01, L02, L11, L12, L22]
    float vec[6];
    vec[0] = s0*v0[0]*v0[0] + s1*v1[0]*v1[0] + s2*v2[0]*v2[0];
    vec[1] = s0*v0[0]*v0[1] + s1*v1[0]*v1[1] + s2*v2[0]*v2[1];
    vec[2] = s0*v0[0]*v0[2] + s1*v1[0]*v1[2] + s2*v2[0]*v2[2];
    vec[3] = s0*v0[1]*v0[1] + s1*v1[1]*v1[1] + s2*v2[1]*v2[1];
    vec[4] = s0*v0[1]*v0[2] + s1*v1[1]*v1[2] + s2*v2[1]*v2[2];
    vec[5] = s0*v0[2]*v0[2] + s1*v1[2]*v1[2] + s2*v2[2]*v2[2];

    // ---- diffusion step scalars (tables are tiny; L2/L1-hot) ----
    const float beta_t   = betas[ti];
    const float beta_cap = betas[beta_m2_idx];   // betas[-2]
    float alpha = 1.0f - beta_t;
    alpha = fmaxf(alpha, 1.0f - beta_cap);
    const float alpha_bar = alpha_bars[ti];
    const float sigma     = sigmas[ti];

    const float coef  = rsqrtf(alpha + 1e-8f);
    const float scale = (1.0f - alpha) * rsqrtf(1.0f - alpha_bar + 1e-8f);
    const float zg    = (tv > 1) ? 1.0f : 0.0f;

    // ---- per-component output (write back into s_lt, reuse buffer) ----
    float* row_lt = &s_lt[tid * 6];
    const float* row_p0 = &s_p0[tid * 6];
    const float* row_z  = &s_z [tid * 6];
    #pragma unroll
    for (int k = 0; k < 6; k++) {
        const float ltv = row_lt[k];
        const float pn  = ltv - 0.5f * (vec[k] + row_p0[k]);
        row_lt[k] = coef * (ltv - scale * pn) + sigma * (zg * row_z[k]);
    }

    __syncthreads();

    // ---- staged coalesced scalar store ----
    {
        float* go = out + base * 6;
        #pragma unroll
        for (int i = tid; i < ROWS_PER_BLOCK * 6; i += ROWS_PER_BLOCK) {
            go[i] = s_lt[i];
        }
    }
}

extern "C" void kernel_launch(void* const* d_in, const int* in_sizes, int n_in,
                              void* d_out, int out_size) {
    const float* lt         = (const float*)d_in[0];
    const float* pl0        = (const float*)d_in[1];
    const float* lat        = (const float*)d_in[2];
    const float* alpha_bars = (const float*)d_in[3];
    const float* betas      = (const float*)d_in[4];
    const float* sigmas     = (const float*)d_in[5];
    const float* zn         = (const float*)d_in[6];
    const int*   tarr       = (const int*)d_in[7];   // int32 on device (JAX x64 off)
    float* out = (float*)d_out;

    const int rows   = in_sizes[7];             // B
    const int nbetas = in_sizes[4];             // NUM_STEPS + 1 = 1001
    const int blocks = rows / ROWS_PER_BLOCK;   // B = 2^20, divisible

    vp_lattice_kernel<<<blocks, ROWS_PER_BLOCK>>>(
        lt, pl0, lat, alpha_bars, betas, sigmas, zn, tarr, out,
        nbetas - 2, nbetas - 1);
}